// round 13
// baseline (speedup 1.0000x reference)
#include <cuda_runtime.h>

#define NN 32
#define CC 256
#define SS 30
#define HWD 256        // 16*16 pixels per frame
#define PP 16          // parts
#define CT 16          // channels per tile
#define PIT 260        // pitch: 16B-aligned rows, 2-way worst-case LDS
#define TILES 4        // tiles per item (item covers 64 channels)
#define SLICES 4       // channel slices per frame
#define NITEMS (NN * SS * SLICES)   // 3840
#define GRID 888       // 148 SMs x 6 resident blocks: one persistent set

__device__ unsigned int g_ticket;

#define CP_ASYNC16(dst, src) \
    asm volatile("cp.async.cg.shared.global [%0], [%1], 16;" :: "r"(dst), "l"(src) : "memory")
#define CP_COMMIT() asm volatile("cp.async.commit_group;" ::: "memory")
#define CP_WAIT(n)  asm volatile("cp.async.wait_group %0;" :: "n"(n) : "memory")

__global__ __launch_bounds__(256, 6)
void part_pool_kernel(const float* __restrict__ x,
                      const void* __restrict__ labels_raw,
                      float* __restrict__ out)
{
    extern __shared__ float tiles[];      // 2 * CT*PIT floats = 33,280 B
    __shared__ float pooled[CT * 17];
    __shared__ unsigned int pk4w[(HWD + PP * 4) / 4];  // byte pixel lists, 4-aligned starts
    __shared__ int off4[PP], fill[PP];
    __shared__ int s_item;

    const int t = threadIdx.x;
    const int w = t >> 5;
    const int l = t & 31;

    // per-lane fixed roles: half-warp owns one part, lane&15 = channel in tile
    const int p   = (w << 1) | (l >> 4);  // part 0..15
    const int cl  = l & 15;               // channel-in-tile
    const int lcl = t >> 4;               // load role: channel
    const int lg  = t & 15;               // load role: pixel group
    const unsigned stile = (unsigned)__cvta_generic_to_shared(tiles);
    unsigned char* pk4 = (unsigned char*)pk4w;

    // ---- block-invariant prologue: first ticket + label-dtype detection.
    // int64 little-endian labels 0..15 -> odd 32-bit words of frame 0 all zero
    // (both candidate layouts keep index 2t+1 in-bounds).
    if (t == 0) s_item = (int)atomicAdd(&g_ticket, 1u);
    const int oddw = ((const int*)labels_raw)[2 * t + 1];
    const int lab64 = !__syncthreads_or(oddw != 0);   // also publishes s_item

    #define LOAD_TILE(tt, buf) do {                                            \
        const float* _row = xf + (size_t)((tt) * CT + lcl) * (SS * HWD);       \
        unsigned _dst = stile + (unsigned)(((buf) * CT + lcl) * (PIT * 4));    \
        _Pragma("unroll")                                                      \
        for (int _k = 0; _k < 4; _k++) {                                       \
            int _g = lg + 16 * _k;                                             \
            CP_ASYNC16(_dst + _g * 16, _row + _g * 4);                         \
        }                                                                      \
        CP_COMMIT();                                                           \
    } while (0)

    for (;;) {
        const int item = s_item;          // barrier-ordered: t0 rewrite is later
        if (item >= NITEMS) break;
        const int f = item >> 2;          // frame
        const int q = item & 3;           // channel slice (64 channels)
        const int n = f / SS;
        const int s = f % SS;

        const float* xf = x + ((size_t)(n * CC + q * (TILES * CT)) * SS + s) * HWD;

        // issue first tile-pair immediately: overlaps all bucketing latency
        LOAD_TILE(0, 0);
        LOAD_TILE(1, 1);

        if (t < PP) fill[t] = 0;
        int myl;
        if (lab64) myl = (int)((const long long*)labels_raw)[(size_t)f * HWD + t];
        else       myl = ((const int*)labels_raw)[(size_t)f * HWD + t];
        myl &= (PP - 1);
        __syncthreads();                  // A: fill zeroed

        const int pos = atomicAdd(&fill[myl], 1);
        __syncthreads();                  // B: fill[p] == cnt[p] final

        const int cN = fill[p];
        const float rc = (cN > 0) ? (1.0f / (float)cN) : 0.0f;
        if (t == 0) {
            int acc = 0;
            #pragma unroll
            for (int pp = 0; pp < PP; pp++) { off4[pp] = acc; acc += (fill[pp] + 3) & ~3; }
        }
        __syncthreads();                  // C: off4[] ready
        pk4[off4[myl] + pos] = (unsigned char)t;   // visible via first tile sync

        // t0 prefetches next ticket; 318-cyc ATOMG hidden behind tile compute.
        // s_item rewrite is ordered before any loop-top read by the final
        // tile sync below (read < barrier A <= C < write < final sync < read').
        if (t == 0) s_item = (int)atomicAdd(&g_ticket, 1u);

        const unsigned int* mylist = pk4w + (off4[p] >> 2);
        const int kW = cN >> 2;           // full 4-pixel words
        const int kR = cN & 3;            // tail pixels in final word

        for (int tt = 0; tt < TILES; tt++) {
            const int buf = tt & 1;
            if (tt + 1 < TILES) CP_WAIT(1);   // tile tt landed, one in flight
            else                CP_WAIT(0);
            __syncthreads();              // tile tt visible to all

            const float* tb = tiles + (buf * CT + cl) * PIT;

            float sum = 0.0f;
            float mx  = -3.0e38f;
            #pragma unroll 2
            for (int k = 0; k < kW; k++) {
                unsigned u = mylist[k];   // 1 broadcast LDS -> 4 pixel ids
                float a = tb[u & 255u];
                float b = tb[(u >> 8) & 255u];
                float c = tb[(u >> 16) & 255u];
                float d = tb[u >> 24];
                sum += (a + b) + (c + d);
                mx = fmaxf(fmaxf(fmaxf(a, b), fmaxf(c, d)), mx);
            }
            if (kR) {                     // tail: only written bytes extracted
                unsigned u = mylist[kW];
                #pragma unroll
                for (int j = 0; j < 3; j++) {
                    if (j < kR) {
                        float v = tb[(u >> (8 * j)) & 255u];
                        sum += v;
                        mx = fmaxf(mx, v);
                    }
                }
            }

            float r = 0.0f;
            if (cN > 0)
                r = sum * rc + fmaxf(mx, -100.0f);  // mean + amax(incl -100)
            pooled[cl * 17 + p] = r;

            __syncthreads();              // pooled ready AND buffer tt consumed

            // coalesced store: thread t -> (channel t>>4, part t&15)
            {
                int cc = t >> 4;
                int pp = t & 15;
                int c  = q * (TILES * CT) + tt * CT + cc;
                out[((size_t)(n * CC + c) * SS + s) * PP + pp] = pooled[cc * 17 + pp];
            }

            // refill this buffer with tile tt+2 (all warps done reading above)
            if (tt + 2 < TILES) LOAD_TILE(tt + 2, buf);
        }
        // final tile's post-compute __syncthreads orders: next item's loop-top
        // s_item read, fill zeroing, buffer reuse, pk4 rewrite. No extra sync.
    }
    #undef LOAD_TILE
}

extern "C" void kernel_launch(void* const* d_in, const int* in_sizes, int n_in,
                              void* d_out, int out_size)
{
    const float* x      = (const float*)d_in[0];
    const void*  labels = d_in[1];
    float*       out    = (float*)d_out;

    cudaFuncSetAttribute(part_pool_kernel,
                         cudaFuncAttributeMaxDynamicSharedMemorySize,
                         2 * CT * PIT * 4);

    void* ctr = nullptr;
    cudaGetSymbolAddress(&ctr, g_ticket);
    cudaMemsetAsync(ctr, 0, sizeof(unsigned int));   // graph-capturable reset

    part_pool_kernel<<<GRID, 256, 2 * CT * PIT * 4>>>(x, labels, out);
}

// round 14
// speedup vs baseline: 1.0638x; 1.0638x over previous
#include <cuda_runtime.h>

#define NN 32
#define CC 256
#define SS 30
#define HWD 256        // 16*16 pixels per frame
#define PP 16          // parts
#define CT 16          // channels per tile
#define PIT 260        // pitch: 16B-aligned rows, 2-way worst-case LDS
#define TILES 4        // tiles per block (block covers 64 channels)
#define SLICES 4       // channel slices per frame

#define CP_ASYNC16(dst, src) \
    asm volatile("cp.async.cg.shared.global.L2::256B [%0], [%1], 16;" :: "r"(dst), "l"(src) : "memory")
#define CP_COMMIT() asm volatile("cp.async.commit_group;" ::: "memory")
#define CP_WAIT(n)  asm volatile("cp.async.wait_group %0;" :: "n"(n) : "memory")

__global__ __launch_bounds__(256, 6)
void part_pool_kernel(const float* __restrict__ x,
                      const void* __restrict__ labels_raw,
                      float* __restrict__ out)
{
    extern __shared__ float tiles[];      // 2 * CT*PIT floats = 33,280 B
    __shared__ float pooled[CT * 17];
    __shared__ unsigned int pk4w[(HWD + PP * 4) / 4];  // byte pixel lists, 4-aligned starts
    __shared__ int off4[PP], fill[PP];

    const int bid = blockIdx.x;           // 0..3839
    const int f   = bid >> 2;             // frame
    const int q   = bid & 3;              // channel slice (64 channels)
    const int n = f / SS;
    const int s = f % SS;
    const int t = threadIdx.x;
    const int w = t >> 5;
    const int l = t & 31;

    // base of this block's channel range for frame (n,s)
    const float* xf = x + ((size_t)(n * CC + q * (TILES * CT)) * SS + s) * HWD;
    const unsigned stile = (unsigned)__cvta_generic_to_shared(tiles);

    // 16B cp.async: thread t loads channel t>>4, 4 groups of 4 pixels (coalesced)
    const int lcl = t >> 4;
    const int lg  = t & 15;
    #define LOAD_TILE(tt, buf) do {                                            \
        const float* _row = xf + (size_t)((tt) * CT + lcl) * (SS * HWD);       \
        unsigned _dst = stile + (unsigned)(((buf) * CT + lcl) * (PIT * 4));    \
        _Pragma("unroll")                                                      \
        for (int _k = 0; _k < 4; _k++) {                                       \
            int _g = lg + 16 * _k;                                             \
            CP_ASYNC16(_dst + _g * 16, _row + _g * 4);                         \
        }                                                                      \
        CP_COMMIT();                                                           \
    } while (0)

    // ---- issue both tile loads BEFORE the prologue (no label dependence):
    // overlaps all bucketing latency with the first 32 KB of DRAM traffic.
    LOAD_TILE(0, 0);
    LOAD_TILE(1, 1);

    // ---- fused label-dtype detection (frame-0 region, in-bounds both layouts):
    // int64 little-endian labels 0..15 -> odd 32-bit words all zero.
    if (t < PP) fill[t] = 0;
    const int oddw = ((const int*)labels_raw)[2 * t + 1];
    const int lab64 = !__syncthreads_or(oddw != 0);   // also orders fill init

    // ---- per-frame label bucketing (single atomic phase) ----
    int myl;
    if (lab64) myl = (int)((const long long*)labels_raw)[(size_t)f * HWD + t];
    else       myl = ((const int*)labels_raw)[(size_t)f * HWD + t];
    myl &= (PP - 1);
    const int pos = atomicAdd(&fill[myl], 1);
    __syncthreads();                      // fill[p] == cnt[p] final

    // per-lane fixed roles: half-warp owns one part, lane&15 = channel in tile
    const int p  = (w << 1) | (l >> 4);   // part 0..15
    const int cl = l & 15;                // channel-in-tile
    const int cN = fill[p];
    const float rc = (cN > 0) ? (1.0f / (float)cN) : 0.0f;

    if (t == 0) {
        int acc = 0;
        #pragma unroll
        for (int pp = 0; pp < PP; pp++) { off4[pp] = acc; acc += (fill[pp] + 3) & ~3; }
    }
    __syncthreads();                      // off4[] ready
    pk4w[0] = pk4w[0];                    // (no-op; keeps pk4w live before write)
    ((unsigned char*)pk4w)[off4[myl] + pos] = (unsigned char)t;   // byte list write
    // pk4w visibility to other warps: covered by the first tile-ready sync.

    const unsigned int* mylist = pk4w + (off4[p] >> 2);
    const int kW = cN >> 2;               // full 4-pixel words
    const int kR = cN & 3;                // tail pixels in final word

    for (int tt = 0; tt < TILES; tt++) {
        const int buf = tt & 1;
        if (tt + 1 < TILES) CP_WAIT(1);   // tile tt landed (one newer in flight)
        else                CP_WAIT(0);
        __syncthreads();                  // tile tt visible to all

        const float* tb = tiles + (buf * CT + cl) * PIT;

        float sum = 0.0f;
        float mx  = -3.0e38f;
        #pragma unroll 4
        for (int k = 0; k < kW; k++) {
            unsigned u = mylist[k];       // 1 broadcast LDS -> 4 pixel ids
            float a = tb[u & 255u];
            float b = tb[(u >> 8) & 255u];
            float c = tb[(u >> 16) & 255u];
            float d = tb[u >> 24];
            sum += (a + b) + (c + d);
            mx = fmaxf(fmaxf(fmaxf(a, b), fmaxf(c, d)), mx);
        }
        if (kR) {                         // tail: only written bytes extracted
            unsigned u = mylist[kW];
            #pragma unroll
            for (int j = 0; j < 3; j++) {
                if (j < kR) {
                    float v = tb[(u >> (8 * j)) & 255u];
                    sum += v;
                    mx = fmaxf(mx, v);
                }
            }
        }

        float r = 0.0f;
        if (cN > 0)
            r = sum * rc + fmaxf(mx, -100.0f);  // mean + amax(incl -100 init)
        pooled[cl * 17 + p] = r;

        __syncthreads();                  // pooled ready AND buffer tt reads done

        // coalesced store: thread t -> (channel t>>4, part t&15)
        {
            int cc = t >> 4;
            int pp = t & 15;
            int c  = q * (TILES * CT) + tt * CT + cc;
            out[((size_t)(n * CC + c) * SS + s) * PP + pp] = pooled[cc * 17 + pp];
        }

        // refill this buffer with tile tt+2 (all warps done reading it above)
        if (tt + 2 < TILES) LOAD_TILE(tt + 2, buf);
    }
    #undef LOAD_TILE
}

extern "C" void kernel_launch(void* const* d_in, const int* in_sizes, int n_in,
                              void* d_out, int out_size)
{
    const float* x      = (const float*)d_in[0];
    const void*  labels = d_in[1];
    float*       out    = (float*)d_out;

    cudaFuncSetAttribute(part_pool_kernel,
                         cudaFuncAttributeMaxDynamicSharedMemorySize,
                         2 * CT * PIT * 4);

    part_pool_kernel<<<NN * SS * SLICES, 256, 2 * CT * PIT * 4>>>(x, labels, out);
}

// round 15
// speedup vs baseline: 1.1103x; 1.0437x over previous
#include <cuda_runtime.h>

#define NN 32
#define CC 256
#define SS 30
#define HWD 256        // 16*16 pixels per frame
#define PP 16          // parts
#define CT 16          // channels per tile
#define PIT 260        // pitch: 16B-aligned rows, 2-way worst-case LDS
#define TILES 2        // tiles per block (block covers 32 channels)
#define SLICES 8       // channel slices per frame

#define CP_ASYNC16(dst, src) \
    asm volatile("cp.async.cg.shared.global [%0], [%1], 16;" :: "r"(dst), "l"(src) : "memory")
#define CP_COMMIT() asm volatile("cp.async.commit_group;" ::: "memory")
#define CP_WAIT(n)  asm volatile("cp.async.wait_group %0;" :: "n"(n) : "memory")

__global__ __launch_bounds__(256, 6)
void part_pool_kernel(const float* __restrict__ x,
                      const void* __restrict__ labels_raw,
                      float* __restrict__ out)
{
    extern __shared__ float tiles[];      // 2 * CT*PIT floats = 33,280 B
    __shared__ float pooled[CT * 17];
    __shared__ unsigned int pk4w[(HWD + PP * 4) / 4];  // byte pixel lists, 4-aligned starts
    __shared__ int off4[PP], fill[PP];

    unsigned char* pk4 = (unsigned char*)pk4w;

    const int bid = blockIdx.x;           // 0..7679
    const int f   = bid >> 3;             // frame
    const int q   = bid & 7;              // channel slice (32 channels)
    const int n = f / SS;
    const int s = f % SS;
    const int t = threadIdx.x;
    const int w = t >> 5;
    const int l = t & 31;

    // base of this block's channel range for frame (n,s)
    const float* xf = x + ((size_t)(n * CC + q * (TILES * CT)) * SS + s) * HWD;
    const unsigned stile = (unsigned)__cvta_generic_to_shared(tiles);

    // 16B cp.async: thread t loads channel t>>4, 4 groups of 4 pixels (coalesced)
    const int lcl = t >> 4;
    const int lg  = t & 15;
    #define LOAD_TILE(tt, buf) do {                                            \
        const float* _row = xf + (size_t)((tt) * CT + lcl) * (SS * HWD);       \
        unsigned _dst = stile + (unsigned)(((buf) * CT + lcl) * (PIT * 4));    \
        _Pragma("unroll")                                                      \
        for (int _k = 0; _k < 4; _k++) {                                       \
            int _g = lg + 16 * _k;                                             \
            CP_ASYNC16(_dst + _g * 16, _row + _g * 4);                         \
        }                                                                      \
        CP_COMMIT();                                                           \
    } while (0)

    // ---- issue both tile loads BEFORE the prologue (no label dependence):
    // overlaps all bucketing latency with the first 32 KB of DRAM traffic.
    LOAD_TILE(0, 0);
    LOAD_TILE(1, 1);

    // ---- fused label-dtype detection (frame-0 region, in-bounds both layouts):
    // int64 little-endian labels 0..15 -> odd 32-bit words all zero.
    if (t < PP) fill[t] = 0;
    const int oddw = ((const int*)labels_raw)[2 * t + 1];
    const int lab64 = !__syncthreads_or(oddw != 0);   // also orders fill init

    // ---- per-frame label bucketing (single atomic phase) ----
    int myl;
    if (lab64) myl = (int)((const long long*)labels_raw)[(size_t)f * HWD + t];
    else       myl = ((const int*)labels_raw)[(size_t)f * HWD + t];
    myl &= (PP - 1);
    const int pos = atomicAdd(&fill[myl], 1);
    __syncthreads();                      // fill[p] == cnt[p] final

    // per-lane fixed roles: half-warp owns one part, lane&15 = channel in tile
    const int p  = (w << 1) | (l >> 4);   // part 0..15
    const int cl = l & 15;                // channel-in-tile
    const int cN = fill[p];
    const float rc = (cN > 0) ? (1.0f / (float)cN) : 0.0f;

    if (t == 0) {
        int acc = 0;
        #pragma unroll
        for (int pp = 0; pp < PP; pp++) { off4[pp] = acc; acc += (fill[pp] + 3) & ~3; }
    }
    __syncthreads();                      // off4[] ready
    pk4[off4[myl] + pos] = (unsigned char)t;   // byte pixel list write
    // pk4 visibility to other warps: covered by the first tile-ready sync.

    const unsigned int* mylist = pk4w + (off4[p] >> 2);
    const int kW = cN >> 2;               // full 4-pixel words
    const int kR = cN & 3;                // tail pixels in final word

    for (int tt = 0; tt < TILES; tt++) {
        const int buf = tt & 1;
        if (tt + 1 < TILES) CP_WAIT(1);   // tile tt landed (one newer in flight)
        else                CP_WAIT(0);
        __syncthreads();                  // tile tt visible to all

        const float* tb = tiles + (buf * CT + cl) * PIT;

        float sum = 0.0f;
        float mx  = -3.0e38f;
        #pragma unroll 2
        for (int k = 0; k < kW; k++) {
            unsigned u = mylist[k];       // 1 broadcast LDS -> 4 pixel ids
            float a = tb[u & 255u];
            float b = tb[(u >> 8) & 255u];
            float c = tb[(u >> 16) & 255u];
            float d = tb[u >> 24];
            sum += (a + b) + (c + d);
            mx = fmaxf(fmaxf(fmaxf(a, b), fmaxf(c, d)), mx);
        }
        if (kR) {                         // tail: only written bytes extracted
            unsigned u = mylist[kW];
            #pragma unroll
            for (int j = 0; j < 3; j++) {
                if (j < kR) {
                    float v = tb[(u >> (8 * j)) & 255u];
                    sum += v;
                    mx = fmaxf(mx, v);
                }
            }
        }

        float r = 0.0f;
        if (cN > 0)
            r = sum * rc + fmaxf(mx, -100.0f);  // mean + amax(incl -100 init)
        pooled[cl * 17 + p] = r;

        __syncthreads();                  // pooled ready AND buffer tt reads done

        // coalesced store: thread t -> (channel t>>4, part t&15)
        {
            int cc = t >> 4;
            int pp = t & 15;
            int c  = q * (TILES * CT) + tt * CT + cc;
            out[((size_t)(n * CC + c) * SS + s) * PP + pp] = pooled[cc * 17 + pp];
        }

        // refill this buffer with tile tt+2 (all warps done reading it above)
        if (tt + 2 < TILES) LOAD_TILE(tt + 2, buf);
    }
    #undef LOAD_TILE
}

extern "C" void kernel_launch(void* const* d_in, const int* in_sizes, int n_in,
                              void* d_out, int out_size)
{
    const float* x      = (const float*)d_in[0];
    const void*  labels = d_in[1];
    float*       out    = (float*)d_out;

    cudaFuncSetAttribute(part_pool_kernel,
                         cudaFuncAttributeMaxDynamicSharedMemorySize,
                         2 * CT * PIT * 4);

    part_pool_kernel<<<NN * SS * SLICES, 256, 2 * CT * PIT * 4>>>(x, labels, out);
}